// round 12
// baseline (speedup 1.0000x reference)
#include <cuda_runtime.h>
#include <cuda_bf16.h>
#include <math.h>
#include <stdint.h>

#define D_MODEL 2048
#define D_HEAD  128
#define NHEADS  16
#define CLAT    512
#define BATCH   2
#define SEQ     2048
#define BS      (BATCH*SEQ)   // 4096
#define HD      (NHEADS*D_HEAD)

typedef __nv_bfloat16 bf16;
typedef __nv_bfloat162 bf162;

// fp32 scratch
__device__ float g_v[(size_t)NHEADS * BS * D_HEAD];
__device__ float g_scores[(size_t)NHEADS * BATCH * SEQ * SEQ];
// bf16 hi/lo operand buffers
__device__ bf16 bx_h[(size_t)BS * D_MODEL],      bx_l[(size_t)BS * D_MODEL];
__device__ bf16 bWd_h[(size_t)CLAT * D_MODEL],   bWd_l[(size_t)CLAT * D_MODEL];
__device__ bf16 bWq_h[(size_t)HD * D_MODEL],     bWq_l[(size_t)HD * D_MODEL];
__device__ bf16 bWuk_h[(size_t)HD * CLAT],       bWuk_l[(size_t)HD * CLAT];
__device__ bf16 bWuv_h[(size_t)HD * CLAT],       bWuv_l[(size_t)HD * CLAT];
__device__ bf16 bWo_h[(size_t)D_MODEL * HD],     bWo_l[(size_t)D_MODEL * HD];
__device__ bf16 blat_h[(size_t)BS * CLAT],       blat_l[(size_t)BS * CLAT];
__device__ bf16 bqh_h[(size_t)BS * HD],          bqh_l[(size_t)BS * HD];
__device__ bf16 bk_h[(size_t)NHEADS * BS * D_HEAD], bk_l[(size_t)NHEADS * BS * D_HEAD];
__device__ bf16 bvT_h[(size_t)NHEADS * BS * D_HEAD], bvT_l[(size_t)NHEADS * BS * D_HEAD];
__device__ bf16 bP_h[(size_t)NHEADS * BATCH * SEQ * SEQ], bP_l[(size_t)NHEADS * BATCH * SEQ * SEQ];
__device__ bf16 bctx_h[(size_t)BS * HD],         bctx_l[(size_t)BS * HD];

// ---------------- primitives ----------------
__device__ __forceinline__ uint32_t smem_u32(const void* p) {
    uint32_t a;
    asm("{ .reg .u64 t; cvta.to.shared.u64 t, %1; cvt.u32.u64 %0, t; }" : "=r"(a) : "l"(p));
    return a;
}
__device__ __forceinline__ void ldsm_x4(uint32_t addr, uint32_t r[4]) {
    asm volatile("ldmatrix.sync.aligned.m8n8.x4.shared.b16 {%0,%1,%2,%3}, [%4];"
        : "=r"(r[0]), "=r"(r[1]), "=r"(r[2]), "=r"(r[3]) : "r"(addr));
}
__device__ __forceinline__ void mma16816(float c[4], const uint32_t a[4], const uint32_t b[2]) {
    asm volatile(
        "mma.sync.aligned.m16n8k16.row.col.f32.bf16.bf16.f32 "
        "{%0,%1,%2,%3}, {%4,%5,%6,%7}, {%8,%9}, {%0,%1,%2,%3};"
        : "+f"(c[0]), "+f"(c[1]), "+f"(c[2]), "+f"(c[3])
        : "r"(a[0]), "r"(a[1]), "r"(a[2]), "r"(a[3]), "r"(b[0]), "r"(b[1]));
}
#define CP16(dst, src) asm volatile("cp.async.cg.shared.global [%0], [%1], 16;" :: "r"(dst), "l"(src))
#define CP_COMMIT() asm volatile("cp.async.commit_group;" ::: "memory")
#define CP_WAIT1() asm volatile("cp.async.wait_group 1;" ::: "memory")
#define CP_WAIT0() asm volatile("cp.async.wait_group 0;" ::: "memory")

__device__ __forceinline__ bf162 split_hi(float a, float b, bf162& lo) {
    bf162 hi = __floats2bfloat162_rn(a, b);
    lo = __floats2bfloat162_rn(a - __bfloat162float(__low2bfloat16(hi)),
                               b - __bfloat162float(__high2bfloat16(hi)));
    return hi;
}

// common smem tile geometry: row stride 80 B (32 k bf16 + pad)
#define ROWB 80
#define TILEB_A (128 * ROWB)          // 10240  (128-row tile)
#define TILEB_B2 (256 * ROWB)         // 20480  (256-row tile, variant B)
#define STAGEB_A (4 * TILEB_A)        // 40960
#define STAGEB_B (2 * TILEB_A + 2 * TILEB_B2)  // 61440
#define SMEM_A_BYTES (2 * STAGEB_A + 128)
#define SMEM_B_BYTES (2 * STAGEB_B + 128)

// ============ variant A: block 128x128, warp tile 64x32 (N=128 GEMMs) ======
template<int OUTMODE>
__global__ void __launch_bounds__(256, 2) gemm_pk(
    const bf16* __restrict__ Ah, const bf16* __restrict__ Al,
    const bf16* __restrict__ Bh, const bf16* __restrict__ Bl,
    float* __restrict__ C, bf16* __restrict__ Ch, bf16* __restrict__ Cl,
    int K, int lda, int ldb, int ldc,
    size_t sAz, size_t sAz2, int zAdiv,
    size_t sBz, int zBmod,
    size_t sCz, size_t sCz2, int zCdiv, int causalMode)
{
    int bn = blockIdx.x, bm = blockIdx.y, z = blockIdx.z;
    if (causalMode == 1 && bn > bm) return;
    int Kend = K;
    if (causalMode == 2) { int lim = (bm + 1) * 128; if (lim < Kend) Kend = lim; }

    size_t aoff = (size_t)(z / zAdiv) * sAz + (size_t)(z % zAdiv) * sAz2;
    size_t boff = (size_t)(z % zBmod) * sBz;
    size_t coff = (size_t)(z / zCdiv) * sCz + (size_t)(z % zCdiv) * sCz2;
    Ah += aoff; Al += aoff; Bh += boff; Bl += boff;

    extern __shared__ char smraw[];
    char* sm = (char*)(((uintptr_t)smraw + 127) & ~(uintptr_t)127);
    uint32_t sbase = smem_u32(sm);

    int tid = threadIdx.x;
    int wid = tid >> 5, lane = tid & 31;
    int m0 = bm * 128, n0 = bn * 128;

    int srow = tid >> 1;
    int sseg = (tid & 1) * 2;
    const bf16* gA  = Ah + (size_t)(m0 + srow) * lda + sseg * 8;
    const bf16* gAl = Al + (size_t)(m0 + srow) * lda + sseg * 8;
    const bf16* gB  = Bh + (size_t)(n0 + srow) * ldb + sseg * 8;
    const bf16* gBl = Bl + (size_t)(n0 + srow) * ldb + sseg * 8;
    uint32_t dOff = (uint32_t)srow * ROWB + (uint32_t)sseg * 16;

    int wm = wid & 1, wn = wid >> 1;
    uint32_t aRow = (uint32_t)(wm * 64 + (lane & 15));
    uint32_t aK8  = (uint32_t)((lane >> 4) * 8);
    uint32_t bRow = (uint32_t)(wn * 32 + (lane & 7) + ((lane >> 4) & 1) * 8);
    uint32_t bK8  = (uint32_t)(((lane >> 3) & 1) * 8);

    float acc[4][4][4];
#pragma unroll
    for (int i = 0; i < 4; i++)
#pragma unroll
        for (int j = 0; j < 4; j++)
#pragma unroll
            for (int r = 0; r < 4; r++) acc[i][j][r] = 0.f;

    int ncha = Kend / 32;

#define STAGE_A(k0, soffst) do { \
    uint32_t d_ = sbase + (soffst) + dOff; \
    CP16(d_,               gA  + (k0)); CP16(d_ + 16,               gA  + (k0) + 8); \
    CP16(d_ + TILEB_A,     gAl + (k0)); CP16(d_ + TILEB_A + 16,     gAl + (k0) + 8); \
    CP16(d_ + 2*TILEB_A,   gB  + (k0)); CP16(d_ + 2*TILEB_A + 16,   gB  + (k0) + 8); \
    CP16(d_ + 3*TILEB_A,   gBl + (k0)); CP16(d_ + 3*TILEB_A + 16,   gBl + (k0) + 8); \
} while (0)

    STAGE_A(0, 0); CP_COMMIT();
    if (ncha > 1) { STAGE_A(32, STAGEB_A); CP_COMMIT(); CP_WAIT1(); }
    else CP_WAIT0();
    __syncthreads();

    for (int c = 0; c < ncha; c++) {
        uint32_t sb = sbase + (uint32_t)(c & 1) * STAGEB_A;
        uint32_t sbAh = sb, sbAl = sb + TILEB_A, sbBh = sb + 2 * TILEB_A, sbBl = sb + 3 * TILEB_A;
#pragma unroll
        for (int ks = 0; ks < 2; ks++) {
            uint32_t k0 = (uint32_t)(ks * 16);
            uint32_t Afh[4][4], Afl[4][4], Bfh[2][4], Bfl[2][4];
#pragma unroll
            for (int im = 0; im < 4; im++) {
                uint32_t ao = (aRow + im * 16) * ROWB + (k0 + aK8) * 2;
                ldsm_x4(sbAh + ao, Afh[im]);
                ldsm_x4(sbAl + ao, Afl[im]);
            }
#pragma unroll
            for (int p = 0; p < 2; p++) {
                uint32_t bo = (bRow + p * 16) * ROWB + (k0 + bK8) * 2;
                ldsm_x4(sbBh + bo, Bfh[p]);
                ldsm_x4(sbBl + bo, Bfl[p]);
            }
#pragma unroll
            for (int im = 0; im < 4; im++)
#pragma unroll
                for (int in_ = 0; in_ < 4; in_++) {
                    int p = in_ >> 1, q = (in_ & 1) * 2;
                    mma16816(acc[im][in_], Afh[im], &Bfh[p][q]);
                    mma16816(acc[im][in_], Afh[im], &Bfl[p][q]);
                    mma16816(acc[im][in_], Afl[im], &Bfh[p][q]);
                }
        }
        __syncthreads();
        if (c + 2 < ncha) {
            STAGE_A((c + 2) * 32, (uint32_t)(c & 1) * STAGEB_A); CP_COMMIT();
            CP_WAIT1(); __syncthreads();
        } else if (c + 1 < ncha) {
            CP_WAIT0(); __syncthreads();
        }
    }
#undef STAGE_A

#pragma unroll
    for (int im = 0; im < 4; im++) {
        int r0 = m0 + wm * 64 + im * 16 + (lane >> 2);
#pragma unroll
        for (int in_ = 0; in_ < 4; in_++) {
            int c0 = n0 + wn * 32 + in_ * 8 + (lane & 3) * 2;
            if (OUTMODE == 0) {
                *(float2*)&C[coff + (size_t)r0 * ldc + c0] =
                    make_float2(acc[im][in_][0], acc[im][in_][1]);
                *(float2*)&C[coff + (size_t)(r0 + 8) * ldc + c0] =
                    make_float2(acc[im][in_][2], acc[im][in_][3]);
            } else {
                bf162 lo0, lo1;
                bf162 hi0 = split_hi(acc[im][in_][0], acc[im][in_][1], lo0);
                bf162 hi1 = split_hi(acc[im][in_][2], acc[im][in_][3], lo1);
                size_t i0 = coff + (size_t)r0 * ldc + c0;
                size_t i1 = coff + (size_t)(r0 + 8) * ldc + c0;
                *(bf162*)&Ch[i0] = hi0; *(bf162*)&Cl[i0] = lo0;
                *(bf162*)&Ch[i1] = hi1; *(bf162*)&Cl[i1] = lo1;
            }
        }
    }
}

// ============ variant B: block 128x256, warp tile 64x64 (big-N GEMMs) ======
// causalMode 1: skip tile iff 2*bn > bm (256-wide cols vs 128-tall rows)
template<int OUTMODE>
__global__ void __launch_bounds__(256) gemm_pk2(
    const bf16* __restrict__ Ah, const bf16* __restrict__ Al,
    const bf16* __restrict__ Bh, const bf16* __restrict__ Bl,
    float* __restrict__ C, bf16* __restrict__ Ch, bf16* __restrict__ Cl,
    int K, int lda, int ldb, int ldc,
    size_t sAz, size_t sAz2, int zAdiv,
    size_t sBz, int zBmod,
    size_t sCz, size_t sCz2, int zCdiv, int causalMode)
{
    int bn = blockIdx.x, bm = blockIdx.y, z = blockIdx.z;
    if (causalMode == 1 && 2 * bn > bm) return;

    size_t aoff = (size_t)(z / zAdiv) * sAz + (size_t)(z % zAdiv) * sAz2;
    size_t boff = (size_t)(z % zBmod) * sBz;
    size_t coff = (size_t)(z / zCdiv) * sCz + (size_t)(z % zCdiv) * sCz2;
    Ah += aoff; Al += aoff; Bh += boff; Bl += boff;

    extern __shared__ char smraw[];
    char* sm = (char*)(((uintptr_t)smraw + 127) & ~(uintptr_t)127);
    uint32_t sbase = smem_u32(sm);

    int tid = threadIdx.x;
    int wid = tid >> 5, lane = tid & 31;
    int m0 = bm * 128, n0 = bn * 256;

    // staging A: thread t -> row t>>1, 32B half (t&1)
    int sArow = tid >> 1;
    int sAseg = (tid & 1) * 2;
    const bf16* gA  = Ah + (size_t)(m0 + sArow) * lda + sAseg * 8;
    const bf16* gAl = Al + (size_t)(m0 + sArow) * lda + sAseg * 8;
    uint32_t dAOff = (uint32_t)sArow * ROWB + (uint32_t)sAseg * 16;
    // staging B: thread t -> row t (256 rows), full 64 B
    const bf16* gB  = Bh + (size_t)(n0 + tid) * ldb;
    const bf16* gBl = Bl + (size_t)(n0 + tid) * ldb;
    uint32_t dBOff = (uint32_t)tid * ROWB;

    int wm = wid & 1, wn = wid >> 1;          // 2 x 4 warp grid, warp tile 64x64
    uint32_t aRow = (uint32_t)(wm * 64 + (lane & 15));
    uint32_t aK8  = (uint32_t)((lane >> 4) * 8);
    uint32_t bRow = (uint32_t)(wn * 64 + (lane & 7) + ((lane >> 4) & 1) * 8);
    uint32_t bK8  = (uint32_t)(((lane >> 3) & 1) * 8);

    float acc[4][8][4];
#pragma unroll
    for (int i = 0; i < 4; i++)
#pragma unroll
        for (int j = 0; j < 8; j++)
#pragma unroll
            for (int r = 0; r < 4; r++) acc[i][j][r] = 0.f;

    int ncha = K / 32;

#define STAGE_B(k0, soffst) do { \
    uint32_t dA_ = sbase + (soffst) + dAOff; \
    CP16(dA_,             gA  + (k0)); CP16(dA_ + 16,             gA  + (k0) + 8); \
    CP16(dA_ + TILEB_A,   gAl + (k0)); CP16(dA_ + TILEB_A + 16,   gAl + (k0) + 8); \
    uint32_t dB_ = sbase + (soffst) + 2 * TILEB_A + dBOff; \
    CP16(dB_,      gB + (k0));      CP16(dB_ + 16, gB + (k0) + 8); \
    CP16(dB_ + 32, gB + (k0) + 16); CP16(dB_ + 48, gB + (k0) + 24); \
    uint32_t dBl_ = dB_ + TILEB_B2; \
    CP16(dBl_,      gBl + (k0));      CP16(dBl_ + 16, gBl + (k0) + 8); \
    CP16(dBl_ + 32, gBl + (k0) + 16); CP16(dBl_ + 48, gBl + (k0) + 24); \
} while (0)

    STAGE_B(0, 0); CP_COMMIT();
    if (ncha > 1) { STAGE_B(32, STAGEB_B); CP_COMMIT(); CP_WAIT1(); }
    else CP_WAIT0();
    __syncthreads();

    for (int c = 0; c < ncha; c++) {
        uint32_t sb = sbase + (uint32_t)(c & 1) * STAGEB_B;
        uint32_t sbAh = sb, sbAl = sb + TILEB_A;
        uint32_t sbBh = sb + 2 * TILEB_A, sbBl = sbBh + TILEB_B2;
#pragma unroll
        for (int ks = 0; ks < 2; ks++) {
            uint32_t k0 = (uint32_t)(ks * 16);
            uint32_t Afh[4][4], Afl[4][4];
#pragma unroll
            for (int im = 0; im < 4; im++) {
                uint32_t ao = (aRow + im * 16) * ROWB + (k0 + aK8) * 2;
                ldsm_x4(sbAh + ao, Afh[im]);
                ldsm_x4(sbAl + ao, Afl[im]);
            }
#pragma unroll
            for (int p = 0; p < 4; p++) {
                uint32_t bo = (bRow + p * 16) * ROWB + (k0 + bK8) * 2;
                uint32_t Bfh[4], Bfl[4];
                ldsm_x4(sbBh + bo, Bfh);
                ldsm_x4(sbBl + bo, Bfl);
#pragma unroll
                for (int im = 0; im < 4; im++)
#pragma unroll
                    for (int hf = 0; hf < 2; hf++) {
                        int q = hf * 2;
                        float* a_ = acc[im][p * 2 + hf];
                        mma16816(a_, Afh[im], &Bfh[q]);
                        mma16816(a_, Afh[im], &Bfl[q]);
                        mma16816(a_, Afl[im], &Bfh[q]);
                    }
            }
        }
        __syncthreads();
        if (c + 2 < ncha) {
            STAGE_B((c + 2) * 32, (uint32_t)(c & 1) * STAGEB_B); CP_COMMIT();
            CP_WAIT1(); __syncthreads();
        } else if (c + 1 < ncha) {
            CP_WAIT0(); __syncthreads();
        }
    }
#undef STAGE_B

#pragma unroll
    for (int im = 0; im < 4; im++) {
        int r0 = m0 + wm * 64 + im * 16 + (lane >> 2);
#pragma unroll
        for (int j = 0; j < 8; j++) {
            int c0 = n0 + wn * 64 + j * 8 + (lane & 3) * 2;
            if (OUTMODE == 0) {
                *(float2*)&C[coff + (size_t)r0 * ldc + c0] =
                    make_float2(acc[im][j][0], acc[im][j][1]);
                *(float2*)&C[coff + (size_t)(r0 + 8) * ldc + c0] =
                    make_float2(acc[im][j][2], acc[im][j][3]);
            } else {
                bf162 lo0, lo1;
                bf162 hi0 = split_hi(acc[im][j][0], acc[im][j][1], lo0);
                bf162 hi1 = split_hi(acc[im][j][2], acc[im][j][3], lo1);
                size_t i0 = coff + (size_t)r0 * ldc + c0;
                size_t i1 = coff + (size_t)(r0 + 8) * ldc + c0;
                *(bf162*)&Ch[i0] = hi0; *(bf162*)&Cl[i0] = lo0;
                *(bf162*)&Ch[i1] = hi1; *(bf162*)&Cl[i1] = lo1;
            }
        }
    }
}

// ---------------- fused fp32 -> (hi,lo) bf16 convert for all 6 inputs -----
#define C0 2097152u   // x       (float4 units)
#define C1 2359296u   // + Wd
#define C2 3407872u   // + Wq
#define C3 3670016u   // + Wuk
#define C4 3932160u   // + Wuv
#define C5 4980736u   // + Wo
__global__ __launch_bounds__(256) void cvt_all_k(
    const float* __restrict__ x, const float* __restrict__ Wd,
    const float* __restrict__ Wq, const float* __restrict__ Wuk,
    const float* __restrict__ Wuv, const float* __restrict__ Wo,
    bf16* xh, bf16* xl, bf16* wdh, bf16* wdl, bf16* wqh, bf16* wql,
    bf16* wukh, bf16* wukl, bf16* wuvh, bf16* wuvl, bf16* woh, bf16* wol)
{
    uint32_t i = blockIdx.x * 256 + threadIdx.x;
    if (i >= C5) return;
    const float* src; bf16 *h, *l; uint32_t o;
    if (i < C0)      { src = x;   h = xh;   l = xl;   o = i; }
    else if (i < C1) { src = Wd;  h = wdh;  l = wdl;  o = i - C0; }
    else if (i < C2) { src = Wq;  h = wqh;  l = wql;  o = i - C1; }
    else if (i < C3) { src = Wuk; h = wukh; l = wukl; o = i - C2; }
    else if (i < C4) { src = Wuv; h = wuvh; l = wuvl; o = i - C3; }
    else             { src = Wo;  h = woh;  l = wol;  o = i - C4; }
    float4 v = *(const float4*)(src + (size_t)o * 4);
    bf162 l0, l1;
    bf162 h0 = split_hi(v.x, v.y, l0);
    bf162 h1 = split_hi(v.z, v.w, l1);
    *(bf162*)&h[(size_t)o * 4]     = h0;
    *(bf162*)&h[(size_t)o * 4 + 2] = h1;
    *(bf162*)&l[(size_t)o * 4]     = l0;
    *(bf162*)&l[(size_t)o * 4 + 2] = l1;
}

// ---------------- transpose + split (block dim3(32,8)) ----------------
__global__ void transpose_split_k(
    const float* __restrict__ in, bf16* __restrict__ oh, bf16* __restrict__ ol,
    int R, int C, size_t inz, size_t outz)
{
    __shared__ float t[32][33];
    const float* pi = in + (size_t)blockIdx.z * inz;
    int c = blockIdx.x * 32 + threadIdx.x;
    int r0 = blockIdx.y * 32 + threadIdx.y;
#pragma unroll
    for (int i = 0; i < 32; i += 8)
        t[threadIdx.y + i][threadIdx.x] = pi[(size_t)(r0 + i) * C + c];
    __syncthreads();
    int rc = blockIdx.y * 32 + threadIdx.x;
    int cr0 = blockIdx.x * 32 + threadIdx.y;
#pragma unroll
    for (int i = 0; i < 32; i += 8) {
        float v = t[threadIdx.x][threadIdx.y + i];
        bf16 hh = __float2bfloat16(v);
        size_t idx = (size_t)blockIdx.z * outz + (size_t)(cr0 + i) * R + rc;
        oh[idx] = hh;
        ol[idx] = __float2bfloat16(v - __bfloat162float(hh));
    }
}

// ---------------- causal softmax: fp32 in, bf16 hi/lo out ----------------
__global__ __launch_bounds__(256) void softmax_causal_k(
    const float* __restrict__ scores, bf16* __restrict__ ph, bf16* __restrict__ pl,
    float scale)
{
    __shared__ float srow[SEQ];
    __shared__ float red[256];
    int r = blockIdx.x;
    int z = r >> 11;
    int s = r & (SEQ - 1);
    const float* p = scores + ((size_t)z * SEQ + (size_t)s) * SEQ;
    size_t obase = ((size_t)z * SEQ + (size_t)s) * SEQ;
    int n = s + 1;
    int tid = threadIdx.x;

    float m = -3.0e38f;
    for (int j = tid; j < n; j += 256) { float vv = p[j]; srow[j] = vv; m = fmaxf(m, vv); }
    red[tid] = m; __syncthreads();
    for (int o = 128; o > 0; o >>= 1) { if (tid < o) red[tid] = fmaxf(red[tid], red[tid + o]); __syncthreads(); }
    m = red[0]; __syncthreads();

    float sum = 0.f;
    for (int j = tid; j < n; j += 256) {
        float e = expf((srow[j] - m) * scale);
        srow[j] = e;
        sum += e;
    }
    red[tid] = sum; __syncthreads();
    for (int o = 128; o > 0; o >>= 1) { if (tid < o) red[tid] += red[tid + o]; __syncthreads(); }
    float inv = 1.f / red[0];

    for (int j = tid; j < n; j += 256) {
        float v = srow[j] * inv;
        bf16 hh = __float2bfloat16(v);
        ph[obase + j] = hh;
        pl[obase + j] = __float2bfloat16(v - __bfloat162float(hh));
    }
    int zend = ((s >> 7) + 1) << 7;
    bf16 z0 = __float2bfloat16(0.f);
    for (int j = n + tid; j < zend; j += 256) { ph[obase + j] = z0; pl[obase + j] = z0; }
}

template<typename T>
static T* symaddr(const void* sym) {
    void* p = nullptr;
    cudaGetSymbolAddress(&p, sym);
    return (T*)p;
}

extern "C" void kernel_launch(void* const* d_in, const int* in_sizes, int n_in,
                              void* d_out, int out_size)
{
    const float* x   = (const float*)d_in[0];
    const float* Wd  = (const float*)d_in[1];
    const float* Wuk = (const float*)d_in[2];
    const float* Wuv = (const float*)d_in[3];
    const float* Wq  = (const float*)d_in[4];
    const float* Wo  = (const float*)d_in[5];
    float* out = (float*)d_out;

    float* vbuf   = symaddr<float>(g_v);
    float* scores = symaddr<float>(g_scores);
    bf16 *xh = symaddr<bf16>(bx_h),   *xl = symaddr<bf16>(bx_l);
    bf16 *wdh = symaddr<bf16>(bWd_h), *wdl = symaddr<bf16>(bWd_l);
    bf16 *wqh = symaddr<bf16>(bWq_h), *wql = symaddr<bf16>(bWq_l);
    bf16 *wukh = symaddr<bf16>(bWuk_h), *wukl = symaddr<bf16>(bWuk_l);
    bf16 *wuvh = symaddr<bf16>(bWuv_h), *wuvl = symaddr<bf16>(bWuv_l);
    bf16 *woh = symaddr<bf16>(bWo_h), *wol = symaddr<bf16>(bWo_l);
    bf16 *lath = symaddr<bf16>(blat_h), *latl = symaddr<bf16>(blat_l);
    bf16 *qhh = symaddr<bf16>(bqh_h), *qhl = symaddr<bf16>(bqh_l);
    bf16 *kh = symaddr<bf16>(bk_h),   *kl = symaddr<bf16>(bk_l);
    bf16 *vth = symaddr<bf16>(bvT_h), *vtl = symaddr<bf16>(bvT_l);
    bf16 *pph = symaddr<bf16>(bP_h),  *ppl = symaddr<bf16>(bP_l);
    bf16 *cth = symaddr<bf16>(bctx_h), *ctl = symaddr<bf16>(bctx_l);

    cudaFuncSetAttribute(gemm_pk<0>,  cudaFuncAttributeMaxDynamicSharedMemorySize, SMEM_A_BYTES);
    cudaFuncSetAttribute(gemm_pk<1>,  cudaFuncAttributeMaxDynamicSharedMemorySize, SMEM_A_BYTES);
    cudaFuncSetAttribute(gemm_pk2<0>, cudaFuncAttributeMaxDynamicSharedMemorySize, SMEM_B_BYTES);
    cudaFuncSetAttribute(gemm_pk2<1>, cudaFuncAttributeMaxDynamicSharedMemorySize, SMEM_B_BYTES);

    dim3 blk(256);
    dim3 tblk(32, 8);
    const size_t SS  = (size_t)SEQ * SEQ;
    const size_t SD  = (size_t)SEQ * D_HEAD;
    const size_t BSD = (size_t)BS * D_HEAD;

    // 0. fused convert (launch #0)
    cvt_all_k<<<(C5 + 255) / 256, blk>>>(x, Wd, Wq, Wuk, Wuv, Wo,
        xh, xl, wdh, wdl, wqh, wql, wukh, wukl, wuvh, wuvl, woh, wol);

    // 1. latents = x @ Wd^T  (B variant, M=4096,N=512,K=2048)
    gemm_pk2<1><<<dim3(CLAT / 256, BS / 128, 1), blk, SMEM_B_BYTES>>>(
        xh, xl, wdh, wdl, nullptr, lath, latl,
        D_MODEL, D_MODEL, D_MODEL, CLAT,
        0, 0, 1, 0, 1, 0, 0, 1, 0);

    // 2. qh = x @ Wq^T  (B variant, M=4096,N=2048,K=2048)
    gemm_pk2<1><<<dim3(HD / 256, BS / 128, 1), blk, SMEM_B_BYTES>>>(
        xh, xl, wqh, wql, nullptr, qhh, qhl,
        D_MODEL, D_MODEL, D_MODEL, HD,
        0, 0, 1, 0, 1, 0, 0, 1, 0);

    // 3. k[h] = latents @ Wuk_h^T  (A variant, N=128)
    gemm_pk<1><<<dim3(1, BS / 128, NHEADS), blk, SMEM_A_BYTES>>>(
        lath, latl, wukh, wukl, nullptr, kh, kl,
        CLAT, CLAT, CLAT, D_HEAD,
        0, 0, 1, (size_t)D_HEAD * CLAT, NHEADS, BSD, 0, 1, 0);

    // 4. v[h] = latents @ Wuv_h^T -> fp32  (A variant, N=128)
    gemm_pk<0><<<dim3(1, BS / 128, NHEADS), blk, SMEM_A_BYTES>>>(
        lath, latl, wuvh, wuvl, vbuf, nullptr, nullptr,
        CLAT, CLAT, CLAT, D_HEAD,
        0, 0, 1, (size_t)D_HEAD * CLAT, NHEADS, BSD, 0, 1, 0);

    // 5. scores = qh_slice @ k_hb^T  (B variant, M=N=2048,K=128, causal)
    //    -> launch index 5: this is what ncu -s 5 -c 1 captures
    gemm_pk2<0><<<dim3(SEQ / 256, SEQ / 128, NHEADS * BATCH), blk, SMEM_B_BYTES>>>(
        qhh, qhl, kh, kl, scores, nullptr, nullptr,
        D_HEAD, HD, D_HEAD, SEQ,
        (size_t)D_HEAD, (size_t)SEQ * HD, 2,
        SD, NHEADS * BATCH, SS, 0, 1, 1);

    // 6. vT = v^T -> bf16 pair (only needed before ctx)
    transpose_split_k<<<dim3(D_HEAD / 32, SEQ / 32, NHEADS * BATCH), tblk>>>(
        vbuf, vth, vtl, SEQ, D_HEAD, SD, SD);

    // 7. softmax -> P bf16 pair
    softmax_causal_k<<<NHEADS * BATCH * SEQ, blk>>>(scores, pph, ppl, 0.08838834764831845f);

    // 8. ctx = P @ vT^T  (A variant, N=128, K trunc)
    gemm_pk<1><<<dim3(1, SEQ / 128, NHEADS * BATCH), blk, SMEM_A_BYTES>>>(
        pph, ppl, vth, vtl, nullptr, cth, ctl,
        SEQ, SEQ, SEQ, HD,
        SS, 0, 1, SD, NHEADS * BATCH,
        (size_t)D_HEAD, (size_t)SEQ * HD, 2, 2);

    // 9. out = ctx @ Wo^T  (B variant, M=4096,N=2048,K=2048)
    gemm_pk2<0><<<dim3(D_MODEL / 256, BS / 128, 1), blk, SMEM_B_BYTES>>>(
        cth, ctl, woh, wol, out, nullptr, nullptr,
        HD, HD, HD, D_MODEL,
        0, 0, 1, 0, 1, 0, 0, 1, 0);
}

// round 14
// speedup vs baseline: 1.1637x; 1.1637x over previous
#include <cuda_runtime.h>
#include <cuda_bf16.h>
#include <math.h>
#include <stdint.h>

#define D_MODEL 2048
#define D_HEAD  128
#define NHEADS  16
#define CLAT    512
#define BATCH   2
#define SEQ     2048
#define BS      (BATCH*SEQ)   // 4096
#define HD      (NHEADS*D_HEAD)

typedef __nv_bfloat16 bf16;
typedef __nv_bfloat162 bf162;

// fp32 scratch
__device__ float g_v[(size_t)NHEADS * BS * D_HEAD];
__device__ float g_scores[(size_t)NHEADS * BATCH * SEQ * SEQ];
// bf16 hi/lo operand buffers
__device__ bf16 bx_h[(size_t)BS * D_MODEL],      bx_l[(size_t)BS * D_MODEL];
__device__ bf16 bWd_h[(size_t)CLAT * D_MODEL],   bWd_l[(size_t)CLAT * D_MODEL];
__device__ bf16 bWq_h[(size_t)HD * D_MODEL],     bWq_l[(size_t)HD * D_MODEL];
__device__ bf16 bWuk_h[(size_t)HD * CLAT],       bWuk_l[(size_t)HD * CLAT];
__device__ bf16 bWuv_h[(size_t)HD * CLAT],       bWuv_l[(size_t)HD * CLAT];
__device__ bf16 bWo_h[(size_t)D_MODEL * HD],     bWo_l[(size_t)D_MODEL * HD];
__device__ bf16 blat_h[(size_t)BS * CLAT],       blat_l[(size_t)BS * CLAT];
__device__ bf16 bqh_h[(size_t)BS * HD],          bqh_l[(size_t)BS * HD];
__device__ bf16 bk_h[(size_t)NHEADS * BS * D_HEAD], bk_l[(size_t)NHEADS * BS * D_HEAD];
__device__ bf16 bvT_h[(size_t)NHEADS * BS * D_HEAD], bvT_l[(size_t)NHEADS * BS * D_HEAD];
__device__ bf16 bP_h[(size_t)NHEADS * BATCH * SEQ * SEQ], bP_l[(size_t)NHEADS * BATCH * SEQ * SEQ];
__device__ bf16 bctx_h[(size_t)BS * HD],         bctx_l[(size_t)BS * HD];

// ---------------- primitives ----------------
__device__ __forceinline__ uint32_t smem_u32(const void* p) {
    uint32_t a;
    asm("{ .reg .u64 t; cvta.to.shared.u64 t, %1; cvt.u32.u64 %0, t; }" : "=r"(a) : "l"(p));
    return a;
}
__device__ __forceinline__ void ldsm_x4(uint32_t addr, uint32_t r[4]) {
    asm volatile("ldmatrix.sync.aligned.m8n8.x4.shared.b16 {%0,%1,%2,%3}, [%4];"
        : "=r"(r[0]), "=r"(r[1]), "=r"(r[2]), "=r"(r[3]) : "r"(addr));
}
__device__ __forceinline__ void mma16816(float c[4], const uint32_t a[4], const uint32_t b[2]) {
    asm volatile(
        "mma.sync.aligned.m16n8k16.row.col.f32.bf16.bf16.f32 "
        "{%0,%1,%2,%3}, {%4,%5,%6,%7}, {%8,%9}, {%0,%1,%2,%3};"
        : "+f"(c[0]), "+f"(c[1]), "+f"(c[2]), "+f"(c[3])
        : "r"(a[0]), "r"(a[1]), "r"(a[2]), "r"(a[3]), "r"(b[0]), "r"(b[1]));
}
#define CP16(dst, src) asm volatile("cp.async.cg.shared.global [%0], [%1], 16;" :: "r"(dst), "l"(src))
#define CP_COMMIT() asm volatile("cp.async.commit_group;" ::: "memory")
#define CP_WAIT1() asm volatile("cp.async.wait_group 1;" ::: "memory")
#define CP_WAIT0() asm volatile("cp.async.wait_group 0;" ::: "memory")

__device__ __forceinline__ bf162 split_hi(float a, float b, bf162& lo) {
    bf162 hi = __floats2bfloat162_rn(a, b);
    lo = __floats2bfloat162_rn(a - __bfloat162float(__low2bfloat16(hi)),
                               b - __bfloat162float(__high2bfloat16(hi)));
    return hi;
}

// SMEM tile: 128 rows x 32 k bf16, row stride 80 B
#define ROWB 80
#define TILEB (128 * ROWB)            // 10240
#define STAGEB (4 * TILEB)            // 40960 per stage (Ah Al Bh Bl)
#define SMEM_BYTES (2 * STAGEB + 128)

// ---------------- cp.async split-bf16 GEMM (block 128x128, warp 64x32) ----
// C[z][M,N] = A[z] @ B[z]^T ; A,B pre-split (hi,lo) bf16 row-major [m][k]/[n][k]
// OUTMODE 0: fp32 C ; OUTMODE 1: bf16 hi/lo pair C
// causalMode: 0 none; 1 skip bn>bm; 2 truncate K at (bm+1)*128
template<int OUTMODE>
__global__ void __launch_bounds__(256, 2) gemm_pk(
    const bf16* __restrict__ Ah, const bf16* __restrict__ Al,
    const bf16* __restrict__ Bh, const bf16* __restrict__ Bl,
    float* __restrict__ C, bf16* __restrict__ Ch, bf16* __restrict__ Cl,
    int K, int lda, int ldb, int ldc,
    size_t sAz, size_t sAz2, int zAdiv,
    size_t sBz, int zBmod,
    size_t sCz, size_t sCz2, int zCdiv, int causalMode)
{
    int bn = blockIdx.x, bm = blockIdx.y, z = blockIdx.z;
    if (causalMode == 1 && bn > bm) return;
    int Kend = K;
    if (causalMode == 2) { int lim = (bm + 1) * 128; if (lim < Kend) Kend = lim; }

    size_t aoff = (size_t)(z / zAdiv) * sAz + (size_t)(z % zAdiv) * sAz2;
    size_t boff = (size_t)(z % zBmod) * sBz;
    size_t coff = (size_t)(z / zCdiv) * sCz + (size_t)(z % zCdiv) * sCz2;
    Ah += aoff; Al += aoff; Bh += boff; Bl += boff;

    extern __shared__ char smraw[];
    char* sm = (char*)(((uintptr_t)smraw + 127) & ~(uintptr_t)127);
    uint32_t sbase = smem_u32(sm);

    int tid = threadIdx.x;
    int wid = tid >> 5, lane = tid & 31;
    int m0 = bm * 128, n0 = bn * 128;

    int srow = tid >> 1;
    int sseg = (tid & 1) * 2;
    const bf16* gA  = Ah + (size_t)(m0 + srow) * lda + sseg * 8;
    const bf16* gAl = Al + (size_t)(m0 + srow) * lda + sseg * 8;
    const bf16* gB  = Bh + (size_t)(n0 + srow) * ldb + sseg * 8;
    const bf16* gBl = Bl + (size_t)(n0 + srow) * ldb + sseg * 8;
    uint32_t dOff = (uint32_t)srow * ROWB + (uint32_t)sseg * 16;

    int wm = wid & 1, wn = wid >> 1;
    uint32_t aRow = (uint32_t)(wm * 64 + (lane & 15));
    uint32_t aK8  = (uint32_t)((lane >> 4) * 8);
    uint32_t bRow = (uint32_t)(wn * 32 + (lane & 7) + ((lane >> 4) & 1) * 8);
    uint32_t bK8  = (uint32_t)(((lane >> 3) & 1) * 8);

    float acc[4][4][4];
#pragma unroll
    for (int i = 0; i < 4; i++)
#pragma unroll
        for (int j = 0; j < 4; j++)
#pragma unroll
            for (int r = 0; r < 4; r++) acc[i][j][r] = 0.f;

    int ncha = Kend / 32;

#define STAGE_A(k0, soffst) do { \
    uint32_t d_ = sbase + (soffst) + dOff; \
    CP16(d_,             gA  + (k0)); CP16(d_ + 16,             gA  + (k0) + 8); \
    CP16(d_ + TILEB,     gAl + (k0)); CP16(d_ + TILEB + 16,     gAl + (k0) + 8); \
    CP16(d_ + 2*TILEB,   gB  + (k0)); CP16(d_ + 2*TILEB + 16,   gB  + (k0) + 8); \
    CP16(d_ + 3*TILEB,   gBl + (k0)); CP16(d_ + 3*TILEB + 16,   gBl + (k0) + 8); \
} while (0)

    STAGE_A(0, 0); CP_COMMIT();
    if (ncha > 1) { STAGE_A(32, STAGEB); CP_COMMIT(); CP_WAIT1(); }
    else CP_WAIT0();
    __syncthreads();

    for (int c = 0; c < ncha; c++) {
        uint32_t sb = sbase + (uint32_t)(c & 1) * STAGEB;
        uint32_t sbAh = sb, sbAl = sb + TILEB, sbBh = sb + 2 * TILEB, sbBl = sb + 3 * TILEB;
#pragma unroll
        for (int ks = 0; ks < 2; ks++) {
            uint32_t k0 = (uint32_t)(ks * 16);
            uint32_t Afh[4][4], Afl[4][4], Bfh[2][4], Bfl[2][4];
#pragma unroll
            for (int im = 0; im < 4; im++) {
                uint32_t ao = (aRow + im * 16) * ROWB + (k0 + aK8) * 2;
                ldsm_x4(sbAh + ao, Afh[im]);
                ldsm_x4(sbAl + ao, Afl[im]);
            }
#pragma unroll
            for (int p = 0; p < 2; p++) {
                uint32_t bo = (bRow + p * 16) * ROWB + (k0 + bK8) * 2;
                ldsm_x4(sbBh + bo, Bfh[p]);
                ldsm_x4(sbBl + bo, Bfl[p]);
            }
#pragma unroll
            for (int im = 0; im < 4; im++)
#pragma unroll
                for (int in_ = 0; in_ < 4; in_++) {
                    int p = in_ >> 1, q = (in_ & 1) * 2;
                    mma16816(acc[im][in_], Afh[im], &Bfh[p][q]);
                    mma16816(acc[im][in_], Afh[im], &Bfl[p][q]);
                    mma16816(acc[im][in_], Afl[im], &Bfh[p][q]);
                }
        }
        __syncthreads();
        if (c + 2 < ncha) {
            STAGE_A((c + 2) * 32, (uint32_t)(c & 1) * STAGEB); CP_COMMIT();
            CP_WAIT1(); __syncthreads();
        } else if (c + 1 < ncha) {
            CP_WAIT0(); __syncthreads();
        }
    }
#undef STAGE_A

#pragma unroll
    for (int im = 0; im < 4; im++) {
        int r0 = m0 + wm * 64 + im * 16 + (lane >> 2);
#pragma unroll
        for (int in_ = 0; in_ < 4; in_++) {
            int c0 = n0 + wn * 32 + in_ * 8 + (lane & 3) * 2;
            if (OUTMODE == 0) {
                *(float2*)&C[coff + (size_t)r0 * ldc + c0] =
                    make_float2(acc[im][in_][0], acc[im][in_][1]);
                *(float2*)&C[coff + (size_t)(r0 + 8) * ldc + c0] =
                    make_float2(acc[im][in_][2], acc[im][in_][3]);
            } else {
                bf162 lo0, lo1;
                bf162 hi0 = split_hi(acc[im][in_][0], acc[im][in_][1], lo0);
                bf162 hi1 = split_hi(acc[im][in_][2], acc[im][in_][3], lo1);
                size_t i0 = coff + (size_t)r0 * ldc + c0;
                size_t i1 = coff + (size_t)(r0 + 8) * ldc + c0;
                *(bf162*)&Ch[i0] = hi0; *(bf162*)&Cl[i0] = lo0;
                *(bf162*)&Ch[i1] = hi1; *(bf162*)&Cl[i1] = lo1;
            }
        }
    }
}

// ---------------- fused fp32 -> (hi,lo) bf16 convert for all 6 inputs -----
#define C0 2097152u   // x       (float4 units)
#define C1 2359296u   // + Wd
#define C2 3407872u   // + Wq
#define C3 3670016u   // + Wuk
#define C4 3932160u   // + Wuv
#define C5 4980736u   // + Wo
__global__ __launch_bounds__(256) void cvt_all_k(
    const float* __restrict__ x, const float* __restrict__ Wd,
    const float* __restrict__ Wq, const float* __restrict__ Wuk,
    const float* __restrict__ Wuv, const float* __restrict__ Wo,
    bf16* xh, bf16* xl, bf16* wdh, bf16* wdl, bf16* wqh, bf16* wql,
    bf16* wukh, bf16* wukl, bf16* wuvh, bf16* wuvl, bf16* woh, bf16* wol)
{
    uint32_t i = blockIdx.x * 256 + threadIdx.x;
    if (i >= C5) return;
    const float* src; bf16 *h, *l; uint32_t o;
    if (i < C0)      { src = x;   h = xh;   l = xl;   o = i; }
    else if (i < C1) { src = Wd;  h = wdh;  l = wdl;  o = i - C0; }
    else if (i < C2) { src = Wq;  h = wqh;  l = wql;  o = i - C1; }
    else if (i < C3) { src = Wuk; h = wukh; l = wukl; o = i - C2; }
    else if (i < C4) { src = Wuv; h = wuvh; l = wuvl; o = i - C3; }
    else             { src = Wo;  h = woh;  l = wol;  o = i - C4; }
    float4 v = *(const float4*)(src + (size_t)o * 4);
    bf162 l0, l1;
    bf162 h0 = split_hi(v.x, v.y, l0);
    bf162 h1 = split_hi(v.z, v.w, l1);
    *(bf162*)&h[(size_t)o * 4]     = h0;
    *(bf162*)&h[(size_t)o * 4 + 2] = h1;
    *(bf162*)&l[(size_t)o * 4]     = l0;
    *(bf162*)&l[(size_t)o * 4 + 2] = l1;
}

// ---------------- transpose + split (block dim3(32,8)) ----------------
__global__ void transpose_split_k(
    const float* __restrict__ in, bf16* __restrict__ oh, bf16* __restrict__ ol,
    int R, int C, size_t inz, size_t outz)
{
    __shared__ float t[32][33];
    const float* pi = in + (size_t)blockIdx.z * inz;
    int c = blockIdx.x * 32 + threadIdx.x;
    int r0 = blockIdx.y * 32 + threadIdx.y;
#pragma unroll
    for (int i = 0; i < 32; i += 8)
        t[threadIdx.y + i][threadIdx.x] = pi[(size_t)(r0 + i) * C + c];
    __syncthreads();
    int rc = blockIdx.y * 32 + threadIdx.x;
    int cr0 = blockIdx.x * 32 + threadIdx.y;
#pragma unroll
    for (int i = 0; i < 32; i += 8) {
        float v = t[threadIdx.x][threadIdx.y + i];
        bf16 hh = __float2bfloat16(v);
        size_t idx = (size_t)blockIdx.z * outz + (size_t)(cr0 + i) * R + rc;
        oh[idx] = hh;
        ol[idx] = __float2bfloat16(v - __bfloat162float(hh));
    }
}

// ---------------- causal softmax: fp32 in, bf16 hi/lo out ----------------
__global__ __launch_bounds__(256) void softmax_causal_k(
    const float* __restrict__ scores, bf16* __restrict__ ph, bf16* __restrict__ pl,
    float scale)
{
    __shared__ float srow[SEQ];
    __shared__ float red[256];
    int r = blockIdx.x;
    int z = r >> 11;
    int s = r & (SEQ - 1);
    const float* p = scores + ((size_t)z * SEQ + (size_t)s) * SEQ;
    size_t obase = ((size_t)z * SEQ + (size_t)s) * SEQ;
    int n = s + 1;
    int tid = threadIdx.x;

    float m = -3.0e38f;
    for (int j = tid; j < n; j += 256) { float vv = p[j]; srow[j] = vv; m = fmaxf(m, vv); }
    red[tid] = m; __syncthreads();
    for (int o = 128; o > 0; o >>= 1) { if (tid < o) red[tid] = fmaxf(red[tid], red[tid + o]); __syncthreads(); }
    m = red[0]; __syncthreads();

    float sum = 0.f;
    for (int j = tid; j < n; j += 256) {
        float e = expf((srow[j] - m) * scale);
        srow[j] = e;
        sum += e;
    }
    red[tid] = sum; __syncthreads();
    for (int o = 128; o > 0; o >>= 1) { if (tid < o) red[tid] += red[tid + o]; __syncthreads(); }
    float inv = 1.f / red[0];

    for (int j = tid; j < n; j += 256) {
        float v = srow[j] * inv;
        bf16 hh = __float2bfloat16(v);
        ph[obase + j] = hh;
        pl[obase + j] = __float2bfloat16(v - __bfloat162float(hh));
    }
    int zend = ((s >> 7) + 1) << 7;
    bf16 z0 = __float2bfloat16(0.f);
    for (int j = n + tid; j < zend; j += 256) { ph[obase + j] = z0; pl[obase + j] = z0; }
}

template<typename T>
static T* symaddr(const void* sym) {
    void* p = nullptr;
    cudaGetSymbolAddress(&p, sym);
    return (T*)p;
}

extern "C" void kernel_launch(void* const* d_in, const int* in_sizes, int n_in,
                              void* d_out, int out_size)
{
    const float* x   = (const float*)d_in[0];
    const float* Wd  = (const float*)d_in[1];
    const float* Wuk = (const float*)d_in[2];
    const float* Wuv = (const float*)d_in[3];
    const float* Wq  = (const float*)d_in[4];
    const float* Wo  = (const float*)d_in[5];
    float* out = (float*)d_out;

    float* vbuf   = symaddr<float>(g_v);
    float* scores = symaddr<float>(g_scores);
    bf16 *xh = symaddr<bf16>(bx_h),   *xl = symaddr<bf16>(bx_l);
    bf16 *wdh = symaddr<bf16>(bWd_h), *wdl = symaddr<bf16>(bWd_l);
    bf16 *wqh = symaddr<bf16>(bWq_h), *wql = symaddr<bf16>(bWq_l);
    bf16 *wukh = symaddr<bf16>(bWuk_h), *wukl = symaddr<bf16>(bWuk_l);
    bf16 *wuvh = symaddr<bf16>(bWuv_h), *wuvl = symaddr<bf16>(bWuv_l);
    bf16 *woh = symaddr<bf16>(bWo_h), *wol = symaddr<bf16>(bWo_l);
    bf16 *lath = symaddr<bf16>(blat_h), *latl = symaddr<bf16>(blat_l);
    bf16 *qhh = symaddr<bf16>(bqh_h), *qhl = symaddr<bf16>(bqh_l);
    bf16 *kh = symaddr<bf16>(bk_h),   *kl = symaddr<bf16>(bk_l);
    bf16 *vth = symaddr<bf16>(bvT_h), *vtl = symaddr<bf16>(bvT_l);
    bf16 *pph = symaddr<bf16>(bP_h),  *ppl = symaddr<bf16>(bP_l);
    bf16 *cth = symaddr<bf16>(bctx_h), *ctl = symaddr<bf16>(bctx_l);

    cudaFuncSetAttribute(gemm_pk<0>, cudaFuncAttributeMaxDynamicSharedMemorySize, SMEM_BYTES);
    cudaFuncSetAttribute(gemm_pk<1>, cudaFuncAttributeMaxDynamicSharedMemorySize, SMEM_BYTES);

    dim3 blk(256);
    dim3 tblk(32, 8);
    const size_t SS  = (size_t)SEQ * SEQ;
    const size_t SD  = (size_t)SEQ * D_HEAD;
    const size_t BSD = (size_t)BS * D_HEAD;

    // 0. fused convert
    cvt_all_k<<<(C5 + 255) / 256, blk>>>(x, Wd, Wq, Wuk, Wuv, Wo,
        xh, xl, wdh, wdl, wqh, wql, wukh, wukl, wuvh, wuvl, woh, wol);

    // 1. latents = x @ Wd^T  (M=4096,N=512,K=2048)
    gemm_pk<1><<<dim3(CLAT / 128, BS / 128, 1), blk, SMEM_BYTES>>>(
        xh, xl, wdh, wdl, nullptr, lath, latl,
        D_MODEL, D_MODEL, D_MODEL, CLAT,
        0, 0, 1, 0, 1, 0, 0, 1, 0);

    // 2. qh = x @ Wq^T  (M=4096,N=2048,K=2048)
    gemm_pk<1><<<dim3(HD / 128, BS / 128, 1), blk, SMEM_BYTES>>>(
        xh, xl, wqh, wql, nullptr, qhh, qhl,
        D_MODEL, D_MODEL, D_MODEL, HD,
        0, 0, 1, 0, 1, 0, 0, 1, 0);

    // 3. k[h] = latents @ Wuk_h^T  (N=128)
    gemm_pk<1><<<dim3(1, BS / 128, NHEADS), blk, SMEM_BYTES>>>(
        lath, latl, wukh, wukl, nullptr, kh, kl,
        CLAT, CLAT, CLAT, D_HEAD,
        0, 0, 1, (size_t)D_HEAD * CLAT, NHEADS, BSD, 0, 1, 0);

    // 4. v[h] = latents @ Wuv_h^T -> fp32  (N=128)
    gemm_pk<0><<<dim3(1, BS / 128, NHEADS), blk, SMEM_BYTES>>>(
        lath, latl, wuvh, wuvl, vbuf, nullptr, nullptr,
        CLAT, CLAT, CLAT, D_HEAD,
        0, 0, 1, (size_t)D_HEAD * CLAT, NHEADS, BSD, 0, 1, 0);

    // 5. scores = qh_slice @ k_hb^T  (M=N=2048,K=128, causal)  <- ncu -s 5
    gemm_pk<0><<<dim3(SEQ / 128, SEQ / 128, NHEADS * BATCH), blk, SMEM_BYTES>>>(
        qhh, qhl, kh, kl, scores, nullptr, nullptr,
        D_HEAD, HD, D_HEAD, SEQ,
        (size_t)D_HEAD, (size_t)SEQ * HD, 2,
        SD, NHEADS * BATCH, SS, 0, 1, 1);

    // 6. vT = v^T -> bf16 pair
    transpose_split_k<<<dim3(D_HEAD / 32, SEQ / 32, NHEADS * BATCH), tblk>>>(
        vbuf, vth, vtl, SEQ, D_HEAD, SD, SD);

    // 7. softmax -> P bf16 pair
    softmax_causal_k<<<NHEADS * BATCH * SEQ, blk>>>(scores, pph, ppl, 0.08838834764831845f);

    // 8. ctx = P @ vT^T  (N=128, K trunc)
    gemm_pk<1><<<dim3(1, SEQ / 128, NHEADS * BATCH), blk, SMEM_BYTES>>>(
        pph, ppl, vth, vtl, nullptr, cth, ctl,
        SEQ, SEQ, SEQ, HD,
        SS, 0, 1, SD, NHEADS * BATCH,
        (size_t)D_HEAD, (size_t)SEQ * HD, 2, 2);

    // 9. out = ctx @ Wo^T  (M=4096,N=2048,K=2048)
    gemm_pk<0><<<dim3(D_MODEL / 128, BS / 128, 1), blk, SMEM_BYTES>>>(
        cth, ctl, woh, wol, out, nullptr, nullptr,
        HD, HD, HD, D_MODEL,
        0, 0, 1, 0, 1, 0, 0, 1, 0);
}

// round 16
// speedup vs baseline: 1.1674x; 1.0032x over previous
#include <cuda_runtime.h>
#include <cuda_bf16.h>
#include <math.h>
#include <stdint.h>

#define D_MODEL 2048
#define D_HEAD  128
#define NHEADS  16
#define CLAT    512
#define BATCH   2
#define SEQ     2048
#define BS      (BATCH*SEQ)   // 4096
#define HD      (NHEADS*D_HEAD)

typedef __nv_bfloat16 bf16;
typedef __nv_bfloat162 bf162;

// fp32 scratch
__device__ float g_v[(size_t)NHEADS * BS * D_HEAD];
__device__ float g_scores[(size_t)NHEADS * BATCH * SEQ * SEQ];
// bf16 hi/lo operand buffers
__device__ bf16 bx_h[(size_t)BS * D_MODEL],      bx_l[(size_t)BS * D_MODEL];
__device__ bf16 bWd_h[(size_t)CLAT * D_MODEL],   bWd_l[(size_t)CLAT * D_MODEL];
__device__ bf16 bWq_h[(size_t)HD * D_MODEL],     bWq_l[(size_t)HD * D_MODEL];
__device__ bf16 bWuk_h[(size_t)HD * CLAT],       bWuk_l[(size_t)HD * CLAT];
__device__ bf16 bWuv_h[(size_t)HD * CLAT],       bWuv_l[(size_t)HD * CLAT];
__device__ bf16 bWo_h[(size_t)D_MODEL * HD],     bWo_l[(size_t)D_MODEL * HD];
__device__ bf16 blat_h[(size_t)BS * CLAT],       blat_l[(size_t)BS * CLAT];
__device__ bf16 bqh_h[(size_t)BS * HD],          bqh_l[(size_t)BS * HD];
__device__ bf16 bk_h[(size_t)NHEADS * BS * D_HEAD], bk_l[(size_t)NHEADS * BS * D_HEAD];
__device__ bf16 bvT_h[(size_t)NHEADS * BS * D_HEAD], bvT_l[(size_t)NHEADS * BS * D_HEAD];
__device__ bf16 bP_h[(size_t)NHEADS * BATCH * SEQ * SEQ], bP_l[(size_t)NHEADS * BATCH * SEQ * SEQ];
__device__ bf16 bctx_h[(size_t)BS * HD],         bctx_l[(size_t)BS * HD];

// ---------------- primitives ----------------
__device__ __forceinline__ uint32_t smem_u32(const void* p) {
    uint32_t a;
    asm("{ .reg .u64 t; cvta.to.shared.u64 t, %1; cvt.u32.u64 %0, t; }" : "=r"(a) : "l"(p));
    return a;
}
__device__ __forceinline__ void ldsm_x4(uint32_t addr, uint32_t r[4]) {
    asm volatile("ldmatrix.sync.aligned.m8n8.x4.shared.b16 {%0,%1,%2,%3}, [%4];"
        : "=r"(r[0]), "=r"(r[1]), "=r"(r[2]), "=r"(r[3]) : "r"(addr));
}
__device__ __forceinline__ void mma16816(float c[4], const uint32_t a[4], const uint32_t b[2]) {
    asm volatile(
        "mma.sync.aligned.m16n8k16.row.col.f32.bf16.bf16.f32 "
        "{%0,%1,%2,%3}, {%4,%5,%6,%7}, {%8,%9}, {%0,%1,%2,%3};"
        : "+f"(c[0]), "+f"(c[1]), "+f"(c[2]), "+f"(c[3])
        : "r"(a[0]), "r"(a[1]), "r"(a[2]), "r"(a[3]), "r"(b[0]), "r"(b[1]));
}
#define CP16(dst, src) asm volatile("cp.async.cg.shared.global [%0], [%1], 16;" :: "r"(dst), "l"(src))
#define CP_COMMIT() asm volatile("cp.async.commit_group;" ::: "memory")
#define CP_WAIT2() asm volatile("cp.async.wait_group 2;" ::: "memory")
#define CP_WAIT1() asm volatile("cp.async.wait_group 1;" ::: "memory")
#define CP_WAIT0() asm volatile("cp.async.wait_group 0;" ::: "memory")

__device__ __forceinline__ bf162 split_hi(float a, float b, bf162& lo) {
    bf162 hi = __floats2bfloat162_rn(a, b);
    lo = __floats2bfloat162_rn(a - __bfloat162float(__low2bfloat16(hi)),
                               b - __bfloat162float(__high2bfloat16(hi)));
    return hi;
}

// SMEM tile: 128 rows x 32 k bf16, row stride 80 B
#define ROWB 80
#define TILEB (128 * ROWB)            // 10240
#define STAGEB (4 * TILEB)            // 40960 per stage (Ah Al Bh Bl)
#define NSTAGE 4
#define SMEM_BYTES (NSTAGE * STAGEB + 128)   // 163968 -> 1 block/SM

// ---------------- cp.async split-bf16 GEMM (block 128x128, warp 64x32) ----
// 4-stage pipeline, ONE __syncthreads per K-chunk.
// C[z][M,N] = A[z] @ B[z]^T ; A,B pre-split (hi,lo) bf16 row-major [m][k]/[n][k]
// OUTMODE 0: fp32 C ; OUTMODE 1: bf16 hi/lo pair C
// causalMode: 0 none; 1 skip bn>bm; 2 truncate K at (bm+1)*128
template<int OUTMODE>
__global__ void __launch_bounds__(256) gemm_pk(
    const bf16* __restrict__ Ah, const bf16* __restrict__ Al,
    const bf16* __restrict__ Bh, const bf16* __restrict__ Bl,
    float* __restrict__ C, bf16* __restrict__ Ch, bf16* __restrict__ Cl,
    int K, int lda, int ldb, int ldc,
    size_t sAz, size_t sAz2, int zAdiv,
    size_t sBz, int zBmod,
    size_t sCz, size_t sCz2, int zCdiv, int causalMode)
{
    int bn = blockIdx.x, bm = blockIdx.y, z = blockIdx.z;
    if (causalMode == 1 && bn > bm) return;
    int Kend = K;
    if (causalMode == 2) { int lim = (bm + 1) * 128; if (lim < Kend) Kend = lim; }

    size_t aoff = (size_t)(z / zAdiv) * sAz + (size_t)(z % zAdiv) * sAz2;
    size_t boff = (size_t)(z % zBmod) * sBz;
    size_t coff = (size_t)(z / zCdiv) * sCz + (size_t)(z % zCdiv) * sCz2;
    Ah += aoff; Al += aoff; Bh += boff; Bl += boff;

    extern __shared__ char smraw[];
    char* sm = (char*)(((uintptr_t)smraw + 127) & ~(uintptr_t)127);
    uint32_t sbase = smem_u32(sm);

    int tid = threadIdx.x;
    int wid = tid >> 5, lane = tid & 31;
    int m0 = bm * 128, n0 = bn * 128;

    int srow = tid >> 1;
    int sseg = (tid & 1) * 2;
    const bf16* gA  = Ah + (size_t)(m0 + srow) * lda + sseg * 8;
    const bf16* gAl = Al + (size_t)(m0 + srow) * lda + sseg * 8;
    const bf16* gB  = Bh + (size_t)(n0 + srow) * ldb + sseg * 8;
    const bf16* gBl = Bl + (size_t)(n0 + srow) * ldb + sseg * 8;
    uint32_t dOff = (uint32_t)srow * ROWB + (uint32_t)sseg * 16;

    int wm = wid & 1, wn = wid >> 1;
    uint32_t aRow = (uint32_t)(wm * 64 + (lane & 15));
    uint32_t aK8  = (uint32_t)((lane >> 4) * 8);
    uint32_t bRow = (uint32_t)(wn * 32 + (lane & 7) + ((lane >> 4) & 1) * 8);
    uint32_t bK8  = (uint32_t)(((lane >> 3) & 1) * 8);

    float acc[4][4][4];
#pragma unroll
    for (int i = 0; i < 4; i++)
#pragma unroll
        for (int j = 0; j < 4; j++)
#pragma unroll
            for (int r = 0; r < 4; r++) acc[i][j][r] = 0.f;

    int ncha = Kend / 32;

#define STAGE_A(k0, soffst) do { \
    uint32_t d_ = sbase + (soffst) + dOff; \
    CP16(d_,             gA  + (k0)); CP16(d_ + 16,             gA  + (k0) + 8); \
    CP16(d_ + TILEB,     gAl + (k0)); CP16(d_ + TILEB + 16,     gAl + (k0) + 8); \
    CP16(d_ + 2*TILEB,   gB  + (k0)); CP16(d_ + 2*TILEB + 16,   gB  + (k0) + 8); \
    CP16(d_ + 3*TILEB,   gBl + (k0)); CP16(d_ + 3*TILEB + 16,   gBl + (k0) + 8); \
} while (0)

    // prologue: stage up to 3 chunks, one commit group each
    {
        int pre = ncha < 3 ? ncha : 3;
        for (int s = 0; s < pre; s++) { STAGE_A(s * 32, (uint32_t)s * STAGEB); CP_COMMIT(); }
    }

    for (int c = 0; c < ncha; c++) {
        int rem = ncha - 1 - c;
        if (rem >= 2) CP_WAIT2();
        else if (rem == 1) CP_WAIT1();
        else CP_WAIT0();
        __syncthreads();               // one barrier per chunk

        uint32_t sb = sbase + (uint32_t)(c & 3) * STAGEB;
        uint32_t sbAh = sb, sbAl = sb + TILEB, sbBh = sb + 2 * TILEB, sbBl = sb + 3 * TILEB;
#pragma unroll
        for (int ks = 0; ks < 2; ks++) {
            uint32_t k0 = (uint32_t)(ks * 16);
            uint32_t Afh[4][4], Afl[4][4], Bfh[2][4], Bfl[2][4];
#pragma unroll
            for (int im = 0; im < 4; im++) {
                uint32_t ao = (aRow + im * 16) * ROWB + (k0 + aK8) * 2;
                ldsm_x4(sbAh + ao, Afh[im]);
                ldsm_x4(sbAl + ao, Afl[im]);
            }
#pragma unroll
            for (int p = 0; p < 2; p++) {
                uint32_t bo = (bRow + p * 16) * ROWB + (k0 + bK8) * 2;
                ldsm_x4(sbBh + bo, Bfh[p]);
                ldsm_x4(sbBl + bo, Bfl[p]);
            }
#pragma unroll
            for (int im = 0; im < 4; im++)
#pragma unroll
                for (int in_ = 0; in_ < 4; in_++) {
                    int p = in_ >> 1, q = (in_ & 1) * 2;
                    mma16816(acc[im][in_], Afh[im], &Bfh[p][q]);
                    mma16816(acc[im][in_], Afh[im], &Bfl[p][q]);
                    mma16816(acc[im][in_], Afl[im], &Bfh[p][q]);
                }
        }

        // stage chunk c+3 into slot (c+3)&3 == (c-1)&3 (safe: last read in
        // compute(c-1), and every warp passed this iteration's barrier after it)
        if (c + 3 < ncha) { STAGE_A((c + 3) * 32, (uint32_t)((c + 3) & 3) * STAGEB); CP_COMMIT(); }
    }
#undef STAGE_A

#pragma unroll
    for (int im = 0; im < 4; im++) {
        int r0 = m0 + wm * 64 + im * 16 + (lane >> 2);
#pragma unroll
        for (int in_ = 0; in_ < 4; in_++) {
            int c0 = n0 + wn * 32 + in_ * 8 + (lane & 3) * 2;
            if (OUTMODE == 0) {
                *(float2*)&C[coff + (size_t)r0 * ldc + c0] =
                    make_float2(acc[im][in_][0], acc[im][in_][1]);
                *(float2*)&C[coff + (size_t)(r0 + 8) * ldc + c0] =
                    make_float2(acc[im][in_][2], acc[im][in_][3]);
            } else {
                bf162 lo0, lo1;
                bf162 hi0 = split_hi(acc[im][in_][0], acc[im][in_][1], lo0);
                bf162 hi1 = split_hi(acc[im][in_][2], acc[im][in_][3], lo1);
                size_t i0 = coff + (size_t)r0 * ldc + c0;
                size_t i1 = coff + (size_t)(r0 + 8) * ldc + c0;
                *(bf162*)&Ch[i0] = hi0; *(bf162*)&Cl[i0] = lo0;
                *(bf162*)&Ch[i1] = hi1; *(bf162*)&Cl[i1] = lo1;
            }
        }
    }
}

// ---------------- fused fp32 -> (hi,lo) bf16 convert for all 6 inputs -----
#define C0 2097152u   // x       (float4 units)
#define C1 2359296u   // + Wd
#define C2 3407872u   // + Wq
#define C3 3670016u   // + Wuk
#define C4 3932160u   // + Wuv
#define C5 4980736u   // + Wo
__global__ __launch_bounds__(256) void cvt_all_k(
    const float* __restrict__ x, const float* __restrict__ Wd,
    const float* __restrict__ Wq, const float* __restrict__ Wuk,
    const float* __restrict__ Wuv, const float* __restrict__ Wo,
    bf16* xh, bf16* xl, bf16* wdh, bf16* wdl, bf16* wqh, bf16* wql,
    bf16* wukh, bf16* wukl, bf16* wuvh, bf16* wuvl, bf16* woh, bf16* wol)
{
    uint32_t i = blockIdx.x * 256 + threadIdx.x;
    if (i >= C5) return;
    const float* src; bf16 *h, *l; uint32_t o;
    if (i < C0)      { src = x;   h = xh;   l = xl;   o = i; }
    else if (i < C1) { src = Wd;  h = wdh;  l = wdl;  o = i - C0; }
    else if (i < C2) { src = Wq;  h = wqh;  l = wql;  o = i - C1; }
    else if (i < C3) { src = Wuk; h = wukh; l = wukl; o = i - C2; }
    else if (i < C4) { src = Wuv; h = wuvh; l = wuvl; o = i - C3; }
    else             { src = Wo;  h = woh;  l = wol;  o = i - C4; }
    float4 v = *(const float4*)(src + (size_t)o * 4);
    bf162 l0, l1;
    bf162 h0 = split_hi(v.x, v.y, l0);
    bf162 h1 = split_hi(v.z, v.w, l1);
    *(bf162*)&h[(size_t)o * 4]     = h0;
    *(bf162*)&h[(size_t)o * 4 + 2] = h1;
    *(bf162*)&l[(size_t)o * 4]     = l0;
    *(bf162*)&l[(size_t)o * 4 + 2] = l1;
}

// ---------------- transpose + split (block dim3(32,8)) ----------------
__global__ void transpose_split_k(
    const float* __restrict__ in, bf16* __restrict__ oh, bf16* __restrict__ ol,
    int R, int C, size_t inz, size_t outz)
{
    __shared__ float t[32][33];
    const float* pi = in + (size_t)blockIdx.z * inz;
    int c = blockIdx.x * 32 + threadIdx.x;
    int r0 = blockIdx.y * 32 + threadIdx.y;
#pragma unroll
    for (int i = 0; i < 32; i += 8)
        t[threadIdx.y + i][threadIdx.x] = pi[(size_t)(r0 + i) * C + c];
    __syncthreads();
    int rc = blockIdx.y * 32 + threadIdx.x;
    int cr0 = blockIdx.x * 32 + threadIdx.y;
#pragma unroll
    for (int i = 0; i < 32; i += 8) {
        float v = t[threadIdx.x][threadIdx.y + i];
        bf16 hh = __float2bfloat16(v);
        size_t idx = (size_t)blockIdx.z * outz + (size_t)(cr0 + i) * R + rc;
        oh[idx] = hh;
        ol[idx] = __float2bfloat16(v - __bfloat162float(hh));
    }
}

// ---------------- causal softmax: fp32 in, bf16 hi/lo out ----------------
__global__ __launch_bounds__(256) void softmax_causal_k(
    const float* __restrict__ scores, bf16* __restrict__ ph, bf16* __restrict__ pl,
    float scale)
{
    __shared__ float srow[SEQ];
    __shared__ float red[256];
    int r = blockIdx.x;
    int z = r >> 11;
    int s = r & (SEQ - 1);
    const float* p = scores + ((size_t)z * SEQ + (size_t)s) * SEQ;
    size_t obase = ((size_t)z * SEQ + (size_t)s) * SEQ;
    int n = s + 1;
    int tid = threadIdx.x;

    float m = -3.0e38f;
    for (int j = tid; j < n; j += 256) { float vv = p[j]; srow[j] = vv; m = fmaxf(m, vv); }
    red[tid] = m; __syncthreads();
    for (int o = 128; o > 0; o >>= 1) { if (tid < o) red[tid] = fmaxf(red[tid], red[tid + o]); __syncthreads(); }
    m = red[0]; __syncthreads();

    float sum = 0.f;
    for (int j = tid; j < n; j += 256) {
        float e = expf((srow[j] - m) * scale);
        srow[j] = e;
        sum += e;
    }
    red[tid] = sum; __syncthreads();
    for (int o = 128; o > 0; o >>= 1) { if (tid < o) red[tid] += red[tid + o]; __syncthreads(); }
    float inv = 1.f / red[0];

    for (int j = tid; j < n; j += 256) {
        float v = srow[j] * inv;
        bf16 hh = __float2bfloat16(v);
        ph[obase + j] = hh;
        pl[obase + j] = __float2bfloat16(v - __bfloat162float(hh));
    }
    int zend = ((s >> 7) + 1) << 7;
    bf16 z0 = __float2bfloat16(0.f);
    for (int j = n + tid; j < zend; j += 256) { ph[obase + j] = z0; pl[obase + j] = z0; }
}

template<typename T>
static T* symaddr(const void* sym) {
    void* p = nullptr;
    cudaGetSymbolAddress(&p, sym);
    return (T*)p;
}

extern "C" void kernel_launch(void* const* d_in, const int* in_sizes, int n_in,
                              void* d_out, int out_size)
{
    const float* x   = (const float*)d_in[0];
    const float* Wd  = (const float*)d_in[1];
    const float* Wuk = (const float*)d_in[2];
    const float* Wuv = (const float*)d_in[3];
    const float* Wq  = (const float*)d_in[4];
    const float* Wo  = (const float*)d_in[5];
    float* out = (float*)d_out;

    float* vbuf   = symaddr<float>(g_v);
    float* scores = symaddr<float>(g_scores);
    bf16 *xh = symaddr<bf16>(bx_h),   *xl = symaddr<bf16>(bx_l);
    bf16 *wdh = symaddr<bf16>(bWd_h), *wdl = symaddr<bf16>(bWd_l);
    bf16 *wqh = symaddr<bf16>(bWq_h), *wql = symaddr<bf16>(bWq_l);
    bf16 *wukh = symaddr<bf16>(bWuk_h), *wukl = symaddr<bf16>(bWuk_l);
    bf16 *wuvh = symaddr<bf16>(bWuv_h), *wuvl = symaddr<bf16>(bWuv_l);
    bf16 *woh = symaddr<bf16>(bWo_h), *wol = symaddr<bf16>(bWo_l);
    bf16 *lath = symaddr<bf16>(blat_h), *latl = symaddr<bf16>(blat_l);
    bf16 *qhh = symaddr<bf16>(bqh_h), *qhl = symaddr<bf16>(bqh_l);
    bf16 *kh = symaddr<bf16>(bk_h),   *kl = symaddr<bf16>(bk_l);
    bf16 *vth = symaddr<bf16>(bvT_h), *vtl = symaddr<bf16>(bvT_l);
    bf16 *pph = symaddr<bf16>(bP_h),  *ppl = symaddr<bf16>(bP_l);
    bf16 *cth = symaddr<bf16>(bctx_h), *ctl = symaddr<bf16>(bctx_l);

    cudaFuncSetAttribute(gemm_pk<0>, cudaFuncAttributeMaxDynamicSharedMemorySize, SMEM_BYTES);
    cudaFuncSetAttribute(gemm_pk<1>, cudaFuncAttributeMaxDynamicSharedMemorySize, SMEM_BYTES);

    dim3 blk(256);
    dim3 tblk(32, 8);
    const size_t SS  = (size_t)SEQ * SEQ;
    const size_t SD  = (size_t)SEQ * D_HEAD;
    const size_t BSD = (size_t)BS * D_HEAD;

    // 0. fused convert
    cvt_all_k<<<(C5 + 255) / 256, blk>>>(x, Wd, Wq, Wuk, Wuv, Wo,
        xh, xl, wdh, wdl, wqh, wql, wukh, wukl, wuvh, wuvl, woh, wol);

    // 1. latents = x @ Wd^T  (M=4096,N=512,K=2048)
    gemm_pk<1><<<dim3(CLAT / 128, BS / 128, 1), blk, SMEM_BYTES>>>(
        xh, xl, wdh, wdl, nullptr, lath, latl,
        D_MODEL, D_MODEL, D_MODEL, CLAT,
        0, 0, 1, 0, 1, 0, 0, 1, 0);

    // 2. qh = x @ Wq^T  (M=4096,N=2048,K=2048)
    gemm_pk<1><<<dim3(HD / 128, BS / 128, 1), blk, SMEM_BYTES>>>(
        xh, xl, wqh, wql, nullptr, qhh, qhl,
        D_MODEL, D_MODEL, D_MODEL, HD,
        0, 0, 1, 0, 1, 0, 0, 1, 0);

    // 3. k[h] = latents @ Wuk_h^T  (N=128)
    gemm_pk<1><<<dim3(1, BS / 128, NHEADS), blk, SMEM_BYTES>>>(
        lath, latl, wukh, wukl, nullptr, kh, kl,
        CLAT, CLAT, CLAT, D_HEAD,
        0, 0, 1, (size_t)D_HEAD * CLAT, NHEADS, BSD, 0, 1, 0);

    // 4. v[h] = latents @ Wuv_h^T -> fp32  (N=128)
    gemm_pk<0><<<dim3(1, BS / 128, NHEADS), blk, SMEM_BYTES>>>(
        lath, latl, wuvh, wuvl, vbuf, nullptr, nullptr,
        CLAT, CLAT, CLAT, D_HEAD,
        0, 0, 1, (size_t)D_HEAD * CLAT, NHEADS, BSD, 0, 1, 0);

    // 5. scores = qh_slice @ k_hb^T  (M=N=2048,K=128, causal)  <- ncu -s 5
    gemm_pk<0><<<dim3(SEQ / 128, SEQ / 128, NHEADS * BATCH), blk, SMEM_BYTES>>>(
        qhh, qhl, kh, kl, scores, nullptr, nullptr,
        D_HEAD, HD, D_HEAD, SEQ,
        (size_t)D_HEAD, (size_t)SEQ * HD, 2,
        SD, NHEADS * BATCH, SS, 0, 1, 1);

    // 6. vT = v^T -> bf16 pair
    transpose_split_k<<<dim3(D_HEAD / 32, SEQ / 32, NHEADS * BATCH), tblk>>>(
        vbuf, vth, vtl, SEQ, D_HEAD, SD, SD);

    // 7. softmax -> P bf16 pair
    softmax_causal_k<<<NHEADS * BATCH * SEQ, blk>>>(scores, pph, ppl, 0.08838834764831845f);

    // 8. ctx = P @ vT^T  (N=128, K trunc)
    gemm_pk<1><<<dim3(1, SEQ / 128, NHEADS * BATCH), blk, SMEM_BYTES>>>(
        pph, ppl, vth, vtl, nullptr, cth, ctl,
        SEQ, SEQ, SEQ, HD,
        SS, 0, 1, SD, NHEADS * BATCH,
        (size_t)D_HEAD, (size_t)SEQ * HD, 2, 2);

    // 9. out = ctx @ Wo^T  (M=4096,N=2048,K=2048)
    gemm_pk<0><<<dim3(D_MODEL / 128, BS / 128, 1), blk, SMEM_BYTES>>>(
        cth, ctl, woh, wol, out, nullptr, nullptr,
        HD, HD, HD, D_MODEL,
        0, 0, 1, 0, 1, 0, 0, 1, 0);
}